// round 6
// baseline (speedup 1.0000x reference)
#include <cuda_runtime.h>
#include <cuda_pipeline.h>
#include <math.h>

// Problem constants
#define Bz 64
#define Tz 512
#define Nz 1024
#define Hz 1024
#define G3 3072
#define Mz (Bz * Tz)

// Scratch: input projection xW = x @ W_ih^T + b_ih : [B*T, 3H]
__device__ float g_xw[(size_t)Mz * G3];

// Packed fp32x2 FMA (sm_103a FFMA2) — identical rounding to two fmaf's.
__device__ __forceinline__ unsigned long long ffma2(unsigned long long a,
                                                    unsigned long long b,
                                                    unsigned long long c) {
    unsigned long long d;
    asm("fma.rn.f32x2 %0, %1, %2, %3;" : "=l"(d) : "l"(a), "l"(b), "l"(c));
    return d;
}
__device__ __forceinline__ float unpack_sum(unsigned long long v) {
    float lo = __uint_as_float((unsigned)(v & 0xffffffffULL));
    float hi = __uint_as_float((unsigned)(v >> 32));
    return lo + hi;
}

// ---------------------------------------------------------------------------
// Kernel 1: g_xw[m,n] = sum_k x[m,k]*W_ih[n,k] + b_ih[n]   (unchanged, 1.9ms)
// ---------------------------------------------------------------------------
__global__ __launch_bounds__(256, 2) void gemm_xw(const float* __restrict__ x,
                                                  const float* __restrict__ W,
                                                  const float* __restrict__ bias) {
    __shared__ __align__(16) double As[2][128 * 16];
    __shared__ __align__(16) double Bs[2][64 * 16];

    const int tid = threadIdx.x;
    const int mb = blockIdx.y * 128;
    const int nb = blockIdx.x * 64;
    const int tn = tid & 15;
    const int tm = tid >> 4;

    unsigned long long acc[8][4];
#pragma unroll
    for (int i = 0; i < 8; i++)
#pragma unroll
        for (int j = 0; j < 4; j++) acc[i][j] = 0ULL;

    auto load_tile = [&](int kt, int buf) {
#pragma unroll
        for (int c = 0; c < 4; c++) {
            int id = tid + 256 * c;
            int row = id >> 3;
            int off = id & 7;
            int swz = (row ^ (row >> 3)) & 7;
            __pipeline_memcpy_async(
                (char*)&As[buf][row * 16] + ((off ^ swz) * 16),
                &x[(size_t)(mb + row) * Nz + kt + off * 4], 16);
        }
#pragma unroll
        for (int c = 0; c < 2; c++) {
            int id = tid + 256 * c;
            int row = id >> 3;
            int off = id & 7;
            int swz = (row ^ (row >> 3)) & 7;
            __pipeline_memcpy_async(
                (char*)&Bs[buf][row * 16] + ((off ^ swz) * 16),
                &W[(size_t)(nb + row) * Nz + kt + off * 4], 16);
        }
        __pipeline_commit();
    };

    load_tile(0, 0);
    load_tile(32, 1);

    for (int it = 0; it < 32; ++it) {
        if (it < 30) __pipeline_wait_prior(1);
        else         __pipeline_wait_prior(0);
        __syncthreads();
        const double* A = As[it & 1];
        const double* B = Bs[it & 1];
#pragma unroll
        for (int kp2 = 0; kp2 < 8; ++kp2) {
            ulonglong2 av[8], bv[4];
#pragma unroll
            for (int i = 0; i < 8; i++) {
                int m = tm + 16 * i;
                int pos = kp2 ^ ((m ^ (m >> 3)) & 7);
                av[i] = *(const ulonglong2*)&A[m * 16 + pos * 2];
            }
#pragma unroll
            for (int j = 0; j < 4; j++) {
                int n = tn + 16 * j;
                int pos = kp2 ^ ((n ^ (n >> 3)) & 7);
                bv[j] = *(const ulonglong2*)&B[n * 16 + pos * 2];
            }
#pragma unroll
            for (int i = 0; i < 8; i++)
#pragma unroll
                for (int j = 0; j < 4; j++) {
                    acc[i][j] = ffma2(av[i].x, bv[j].x, acc[i][j]);
                    acc[i][j] = ffma2(av[i].y, bv[j].y, acc[i][j]);
                }
        }
        __syncthreads();
        if (it + 2 < 32) load_tile((it + 2) * 32, it & 1);
    }

    float bvv[4];
#pragma unroll
    for (int j = 0; j < 4; j++) bvv[j] = bias[nb + tn + 16 * j];
#pragma unroll
    for (int i = 0; i < 8; i++) {
        int m = mb + tm + 16 * i;
#pragma unroll
        for (int j = 0; j < 4; j++) {
            int n = nb + tn + 16 * j;
            g_xw[(size_t)m * G3 + n] = unpack_sum(acc[i][j]) + bvv[j];
        }
    }
}

// ---------------------------------------------------------------------------
// Kernel 2: one GRU step. Batch-per-lane layout, broadcast W.
// Grid 128 CTAs x 128 threads (4 warps).
// Warp w: bg = w&1 (batches bg*32+lane), ch = w>>1 (local cols ch*4..+3).
// Lane accumulates 4 cols x 3 gates = 12 FFMA2 accs over full K.
// W slice [24][1024] (96KB) in smem, broadcast LDS (16B crossbar).
// h staged in smem chunks [64][32] floats, pitch 36 (conflict-free), 4 bufs.
// ---------------------------------------------------------------------------
#define WROW_F 1024                 // floats per w row in smem
#define HP 36                       // h chunk pitch in floats
#define HCHUNK_F (64 * HP)          // floats per h buffer
#define WS_F (24 * WROW_F)          // 24576 floats = 96KB
#define GRU_SMEM_F (WS_F + 4 * HCHUNK_F)   // + 4*2304 = 33792 -> total 133,632B

__global__ __launch_bounds__(128) void gru_step(const float* __restrict__ Whh,
                                                const float* __restrict__ bhh,
                                                const float* __restrict__ mix,
                                                float* __restrict__ out,
                                                int t) {
    extern __shared__ float sm[];
    float* ws = sm;                          // [24][1024]
    float* hb = sm + WS_F;                   // 4 x [64][36]

    const int tid = threadIdx.x;
    const int lane = tid & 31;
    const int wid = tid >> 5;
    const int bg = wid & 1;
    const int ch = wid >> 1;
    const int batch = bg * 32 + lane;
    const int jb = blockIdx.x * 8;
    const size_t TH = (size_t)Tz * Hz;

    unsigned long long acc[12];              // [cl*3 + gate]
#pragma unroll
    for (int r = 0; r < 12; r++) acc[r] = 0ULL;

    if (t > 0) {
        const float* hprev = out + (size_t)(t - 1) * Hz;

        // ---- preload W slice: 24 rows x 1024 floats, 48 16B-chunks/thread ----
#pragma unroll
        for (int c = 0; c < 48; c++) {
            int id = tid + 128 * c;          // 0..6143
            int row = id >> 8;               // 0..23  (= ch*12 + cl*3 + g)
            int off = id & 255;              // 16B chunk
            int rch = row / 12, rem = row % 12;
            int cl = rem / 3, g = rem % 3;
            int j = jb + rch * 4 + cl;
            __pipeline_memcpy_async(
                (char*)(ws + row * WROW_F) + off * 16,
                &Whh[(size_t)(g * Hz + j) * Hz + off * 4], 16);
        }
        // ---- h chunk loader: [64 batches][32 k] -> buf, pitch 36 ----
        auto load_h = [&](int ci, int buf) {
            float* dst = hb + buf * HCHUNK_F;
#pragma unroll
            for (int q = 0; q < 4; q++) {
                int id = tid + 128 * q;      // 0..511
                int b = id >> 3;             // 0..63
                int s = id & 7;              // 16B chunk in row
                __pipeline_memcpy_async(
                    (char*)(dst + b * HP) + s * 16,
                    &hprev[(size_t)b * TH + ci * 32 + s * 4], 16);
            }
            __pipeline_commit();
        };
        load_h(0, 0);                        // flushes W copies too (group 0)
        load_h(1, 1);
        load_h(2, 2);

        const float* wbase = ws + ch * 12 * WROW_F;
        const float* hrow_base0 = hb + batch * HP;

        for (int ci = 0; ci < 32; ++ci) {
            if (ci <= 29)      __pipeline_wait_prior(2);
            else if (ci == 30) __pipeline_wait_prior(1);
            else               __pipeline_wait_prior(0);
            __syncthreads();
            if (ci + 3 <= 31) load_h(ci + 3, (ci + 3) & 3);

            const float* H = hrow_base0 + (ci & 3) * HCHUNK_F;
            const float* Wp = wbase + ci * 32;
#pragma unroll
            for (int s = 0; s < 8; ++s) {
                ulonglong2 hv = *(const ulonglong2*)(H + s * 4);
#pragma unroll
                for (int r = 0; r < 12; ++r) {
                    ulonglong2 wv =
                        *(const ulonglong2*)(Wp + r * WROW_F + s * 4);
                    acc[r] = ffma2(hv.x, wv.x, acc[r]);
                    acc[r] = ffma2(hv.y, wv.y, acc[r]);
                }
            }
        }
    }

    // ---- epilogue: 4 columns per lane ----
#pragma unroll
    for (int cl = 0; cl < 4; ++cl) {
        int j = jb + ch * 4 + cl;
        float hr = unpack_sum(acc[cl * 3 + 0]) + bhh[j];
        float hz = unpack_sum(acc[cl * 3 + 1]) + bhh[Hz + j];
        float hn = unpack_sum(acc[cl * 3 + 2]) + bhh[2 * Hz + j];

        size_t xb = ((size_t)batch * Tz + t) * G3 + j;
        float xr = g_xw[xb];
        float xz = g_xw[xb + Hz];
        float xn = g_xw[xb + 2 * Hz];

        float r = 1.0f / (1.0f + expf(-(xr + hr)));
        float z = 1.0f / (1.0f + expf(-(xz + hz)));
        float n = tanhf(xn + r * hn);

        float hp = (t == 0) ? 0.0f
                            : out[(size_t)batch * TH + (size_t)(t - 1) * Hz + j];
        float hnew = (1.0f - z) * n + z * hp;
        float m = mix[batch * Tz + t];
        float hm = hnew * m + hp * (1.0f - m);

        out[(size_t)batch * TH + (size_t)t * Hz + j] = hm;
        if (t == Tz - 1) {
            out[(size_t)Bz * TH + (size_t)batch * Hz + j] = hm;  // 'o'
        }
    }
}

// ---------------------------------------------------------------------------
extern "C" void kernel_launch(void* const* d_in, const int* in_sizes, int n_in,
                              void* d_out, int out_size) {
    const float* x   = (const float*)d_in[0];
    const float* mix = (const float*)d_in[1];
    const float* Wih = (const float*)d_in[2];
    const float* Whh = (const float*)d_in[3];
    const float* bih = (const float*)d_in[4];
    const float* bhh = (const float*)d_in[5];
    float* out = (float*)d_out;

    const size_t gru_smem = GRU_SMEM_F * sizeof(float);   // 133,632 B
    cudaFuncSetAttribute(gru_step, cudaFuncAttributeMaxDynamicSharedMemorySize,
                         (int)gru_smem);

    dim3 ggrid(G3 / 64, Mz / 128);    // 48 x 256
    gemm_xw<<<ggrid, 256>>>(x, Wih, bih);

    for (int t = 0; t < Tz; t++) {
        gru_step<<<Hz / 8, 128, gru_smem>>>(Whh, bhh, mix, out, t);
    }
}

// round 8
// speedup vs baseline: 1.1734x; 1.1734x over previous
#include <cuda_runtime.h>
#include <cuda_pipeline.h>
#include <math.h>

#define Bz 64
#define Tz 512
#define Nz 1024
#define Hz 1024
#define G3 3072
#define Mz (Bz * Tz)

__device__ float g_xw[(size_t)Mz * G3];

__device__ __forceinline__ unsigned long long ffma2(unsigned long long a,
                                                    unsigned long long b,
                                                    unsigned long long c) {
    unsigned long long d;
    asm("fma.rn.f32x2 %0, %1, %2, %3;" : "=l"(d) : "l"(a), "l"(b), "l"(c));
    return d;
}
__device__ __forceinline__ float unpack_sum(unsigned long long v) {
    float lo = __uint_as_float((unsigned)(v & 0xffffffffULL));
    float hi = __uint_as_float((unsigned)(v >> 32));
    return lo + hi;
}

// ---------------------------------------------------------------------------
// Kernel 1: g_xw = x @ W_ih^T + b_ih   (unchanged; ~1.9ms, near FFMA2 floor)
// ---------------------------------------------------------------------------
__global__ __launch_bounds__(256, 2) void gemm_xw(const float* __restrict__ x,
                                                  const float* __restrict__ W,
                                                  const float* __restrict__ bias) {
    __shared__ __align__(16) double As[2][128 * 16];
    __shared__ __align__(16) double Bs[2][64 * 16];

    const int tid = threadIdx.x;
    const int mb = blockIdx.y * 128;
    const int nb = blockIdx.x * 64;
    const int tn = tid & 15;
    const int tm = tid >> 4;

    unsigned long long acc[8][4];
#pragma unroll
    for (int i = 0; i < 8; i++)
#pragma unroll
        for (int j = 0; j < 4; j++) acc[i][j] = 0ULL;

    auto load_tile = [&](int kt, int buf) {
#pragma unroll
        for (int c = 0; c < 4; c++) {
            int id = tid + 256 * c;
            int row = id >> 3;
            int off = id & 7;
            int swz = (row ^ (row >> 3)) & 7;
            __pipeline_memcpy_async(
                (char*)&As[buf][row * 16] + ((off ^ swz) * 16),
                &x[(size_t)(mb + row) * Nz + kt + off * 4], 16);
        }
#pragma unroll
        for (int c = 0; c < 2; c++) {
            int id = tid + 256 * c;
            int row = id >> 3;
            int off = id & 7;
            int swz = (row ^ (row >> 3)) & 7;
            __pipeline_memcpy_async(
                (char*)&Bs[buf][row * 16] + ((off ^ swz) * 16),
                &W[(size_t)(nb + row) * Nz + kt + off * 4], 16);
        }
        __pipeline_commit();
    };

    load_tile(0, 0);
    load_tile(32, 1);

    for (int it = 0; it < 32; ++it) {
        if (it < 30) __pipeline_wait_prior(1);
        else         __pipeline_wait_prior(0);
        __syncthreads();
        const double* A = As[it & 1];
        const double* B = Bs[it & 1];
#pragma unroll
        for (int kp2 = 0; kp2 < 8; ++kp2) {
            ulonglong2 av[8], bv[4];
#pragma unroll
            for (int i = 0; i < 8; i++) {
                int m = tm + 16 * i;
                int pos = kp2 ^ ((m ^ (m >> 3)) & 7);
                av[i] = *(const ulonglong2*)&A[m * 16 + pos * 2];
            }
#pragma unroll
            for (int j = 0; j < 4; j++) {
                int n = tn + 16 * j;
                int pos = kp2 ^ ((n ^ (n >> 3)) & 7);
                bv[j] = *(const ulonglong2*)&B[n * 16 + pos * 2];
            }
#pragma unroll
            for (int i = 0; i < 8; i++)
#pragma unroll
                for (int j = 0; j < 4; j++) {
                    acc[i][j] = ffma2(av[i].x, bv[j].x, acc[i][j]);
                    acc[i][j] = ffma2(av[i].y, bv[j].y, acc[i][j]);
                }
        }
        __syncthreads();
        if (it + 2 < 32) load_tile((it + 2) * 32, it & 1);
    }

    float bvv[4];
#pragma unroll
    for (int j = 0; j < 4; j++) bvv[j] = bias[nb + tn + 16 * j];
#pragma unroll
    for (int i = 0; i < 8; i++) {
        int m = mb + tm + 16 * i;
#pragma unroll
        for (int j = 0; j < 4; j++) {
            int n = nb + tn + 16 * j;
            g_xw[(size_t)m * G3 + n] = unpack_sum(acc[i][j]) + bvv[j];
        }
    }
}

// ---------------------------------------------------------------------------
// Kernel 2: one GRU step.  512 threads (16 warps = 4/SMSP), 128 CTAs.
// Warp w: ks = w>>2 (K-slice of 256), bg = (w>>1)&1 (batches), ch = w&1
// (4 cols). Lane = batch within bg. 12 FFMA2 accs/lane (4 cols x 3 gates).
// Each ks-group (4 warps, contiguous 128 threads) runs its own double-
// buffered cp.async h pipeline, synced by a named barrier (id ks+1).
// K partials reduced via smem; ks=0 warps run the gate epilogue.
// ---------------------------------------------------------------------------
#define WROW_F 1024
#define WS_F (24 * WROW_F)          // 96KB
#define HP 36                       // h chunk pitch (floats), conflict-free
#define HCHUNK_F (64 * HP)          // 2304 floats per chunk buffer
#define NCHUNKBUF 8                 // 2 per ks-group
#define PPITCH 13                   // partials pitch (floats), conflict-free
#define PART_F (16 * 32 * PPITCH)   // 6656 floats
#define GRU_SMEM_F (WS_F + NCHUNKBUF * HCHUNK_F + PART_F)  // 49664 f = 198,656B

__global__ __launch_bounds__(512) void gru_step(const float* __restrict__ Whh,
                                                const float* __restrict__ bhh,
                                                const float* __restrict__ mix,
                                                float* __restrict__ out,
                                                int t) {
    extern __shared__ float sm[];
    float* ws = sm;                           // [24][1024]
    float* hb = sm + WS_F;                    // 8 x [64][36]
    float* pb = sm + WS_F + NCHUNKBUF * HCHUNK_F;  // [16*32][13]

    const int tid = threadIdx.x;
    const int lane = tid & 31;
    const int w = tid >> 5;
    const int ks = w >> 2;
    const int bg = (w >> 1) & 1;
    const int ch = w & 1;
    const int gtid = tid & 127;               // tid within ks-group
    const int batch = bg * 32 + lane;
    const int jb = blockIdx.x * 8;
    const size_t TH = (size_t)Tz * Hz;
    const int bar_id = ks + 1;

    unsigned long long acc[12];
#pragma unroll
    for (int r = 0; r < 12; r++) acc[r] = 0ULL;

    if (t > 0) {
        const float* hprev = out + (size_t)(t - 1) * Hz;

        // ---- W slice preload: 24 rows x 1024 floats, 12 chunks/thread ----
#pragma unroll
        for (int c = 0; c < 12; c++) {
            int id = tid + 512 * c;           // 0..6143
            int row = id >> 8;                // 0..23 = rch*12 + cl*3 + g
            int off = id & 255;
            int rch = row / 12, rem = row % 12;
            int cl = rem / 3, g = rem % 3;
            int j = jb + rch * 4 + cl;
            __pipeline_memcpy_async(
                (char*)(ws + row * WROW_F) + off * 16,
                &Whh[(size_t)(g * Hz + j) * Hz + off * 4], 16);
        }
        __pipeline_commit();                  // group: W

        // ---- group-local h chunk loader: chunk ci -> [64][32], pitch 36 ----
        auto load_h = [&](int ci, int bufsel) {
            float* dst = hb + (ks * 2 + bufsel) * HCHUNK_F;
#pragma unroll
            for (int q = 0; q < 4; q++) {
                int id = gtid + 128 * q;      // 0..511
                int b = id >> 3;
                int s = id & 7;
                __pipeline_memcpy_async(
                    (char*)(dst + b * HP) + s * 16,
                    &hprev[(size_t)b * TH + ci * 32 + s * 4], 16);
            }
            __pipeline_commit();
        };
        const int ci0 = ks * 8;
        load_h(ci0 + 0, 0);
        load_h(ci0 + 1, 1);

        __pipeline_wait_prior(2);             // W copies done (this thread)
        __syncthreads();                      // W done CTA-wide

        const float* wbase = ws + ch * 12 * WROW_F;

        for (int i = 0; i < 8; ++i) {
            if (i < 7) __pipeline_wait_prior(1);
            else       __pipeline_wait_prior(0);
            asm volatile("bar.sync %0, 128;" :: "r"(bar_id) : "memory");

            const float* H = hb + (ks * 2 + (i & 1)) * HCHUNK_F + batch * HP;
            const float* Wp = wbase + (ci0 + i) * 32;
#pragma unroll
            for (int s = 0; s < 8; ++s) {
                ulonglong2 hv = *(const ulonglong2*)(H + s * 4);
#pragma unroll
                for (int r = 0; r < 12; ++r) {
                    ulonglong2 wv =
                        *(const ulonglong2*)(Wp + r * WROW_F + s * 4);
                    acc[r] = ffma2(hv.x, wv.x, acc[r]);
                    acc[r] = ffma2(hv.y, wv.y, acc[r]);
                }
            }
            asm volatile("bar.sync %0, 128;" :: "r"(bar_id) : "memory");
            if (i + 2 < 8) load_h(ci0 + i + 2, i & 1);
        }

        // ---- write K-partials ----
        float* pp = pb + (w * 32 + lane) * PPITCH;
#pragma unroll
        for (int r = 0; r < 12; ++r) pp[r] = unpack_sum(acc[r]);
        __syncthreads();
    }

    // ---- epilogue by ks=0 warps (w 0..3): 64 batches x 8 cols ----
    if (w < 4) {
        // here bg=(w>>1)&1, ch=w&1 as above; batch = bg*32+lane
#pragma unroll
        for (int cl = 0; cl < 4; ++cl) {
            int j = jb + ch * 4 + cl;
            float hr = bhh[j], hz = bhh[Hz + j], hn = bhh[2 * Hz + j];
            if (t > 0) {
#pragma unroll
                for (int kss = 0; kss < 4; ++kss) {
                    const float* pp = pb + ((kss * 4 + w) * 32 + lane) * PPITCH;
                    hr += pp[cl * 3 + 0];
                    hz += pp[cl * 3 + 1];
                    hn += pp[cl * 3 + 2];
                }
            }
            size_t xb = ((size_t)batch * Tz + t) * G3 + j;
            float xr = g_xw[xb];
            float xz = g_xw[xb + Hz];
            float xn = g_xw[xb + 2 * Hz];

            float r = 1.0f / (1.0f + expf(-(xr + hr)));
            float z = 1.0f / (1.0f + expf(-(xz + hz)));
            float n = tanhf(xn + r * hn);

            float hp = (t == 0) ? 0.0f
                                : out[(size_t)batch * TH + (size_t)(t - 1) * Hz + j];
            float hnew = (1.0f - z) * n + z * hp;
            float m = mix[batch * Tz + t];
            float hm = hnew * m + hp * (1.0f - m);

            out[(size_t)batch * TH + (size_t)t * Hz + j] = hm;
            if (t == Tz - 1) {
                out[(size_t)Bz * TH + (size_t)batch * Hz + j] = hm;  // 'o'
            }
        }
    }
}

// ---------------------------------------------------------------------------
extern "C" void kernel_launch(void* const* d_in, const int* in_sizes, int n_in,
                              void* d_out, int out_size) {
    const float* x   = (const float*)d_in[0];
    const float* mix = (const float*)d_in[1];
    const float* Wih = (const float*)d_in[2];
    const float* Whh = (const float*)d_in[3];
    const float* bih = (const float*)d_in[4];
    const float* bhh = (const float*)d_in[5];
    float* out = (float*)d_out;

    const size_t gru_smem = GRU_SMEM_F * sizeof(float);   // 198,656 B
    cudaFuncSetAttribute(gru_step, cudaFuncAttributeMaxDynamicSharedMemorySize,
                         (int)gru_smem);

    dim3 ggrid(G3 / 64, Mz / 128);
    gemm_xw<<<ggrid, 256>>>(x, Wih, bih);

    for (int t = 0; t < Tz; t++) {
        gru_step<<<Hz / 8, 512, gru_smem>>>(Whh, bhh, mix, out, t);
    }
}